// round 15
// baseline (speedup 1.0000x reference)
#include <cuda_runtime.h>
#include <cuda_fp16.h>
#include <math.h>
#include <stdint.h>

#define NB   512
#define NE   300
#define NH   512
#define NM   256
#define NB2  1024
#define NG   2048
#define NHC  2053
#define NT   60

#define KH   512           // h part of K
#define KX   320           // x part of K (300 padded)
#define KB   832           // total B' K
#define NCALL 13           // 13 chunks of 64

#define STAGES 3
#define STAGE_BYTES 24576  // 16KB A + 8KB B
#define GEMM_SMEM (STAGES*STAGE_BYTES)
#define ZS 72              // z-tile row stride (floats), 128x64 tile

__device__ float g_h [NB2 * NH];                   // sorted row order
__device__ float g_c [NB2 * NH];
__device__ float g_hc[NB * NHC];
__device__ float g_e1[NB * NM];
__device__ __half g_Abuf[2][(size_t)NB2 * KH];     // ping-pong h (fp16)
__device__ __half g_B  [(size_t)NG * KB];          // [Wh|Wx] fp16, gate-interleaved N
__device__ __half g_Ax [(size_t)NT * NB2 * KX];    // emb fp16, sorted rows
__device__ int g_perm[NB2];
__device__ int g_pos [NB2];
__device__ int g_slp [NB2];
__device__ int g_Mt  [NT];
__device__ int g_flag[NT][8];                      // per (step, row-tile) arrival count

__device__ __forceinline__ float sigmf(float x) {
    return __fdividef(1.0f, 1.0f + __expf(-x));
}
__device__ __forceinline__ float tanh_fast(float x) {
    float xx = fminf(fmaxf(x, -15.0f), 15.0f);
    float e = __expf(2.0f * xx);
    return __fdividef(e - 1.0f, e + 1.0f);
}

#define SWZ(b) ((b) ^ (((b) >> 3) & 0x70))

__device__ __forceinline__ uint32_t smem_u32(const void* p) {
    uint32_t a;
    asm("{ .reg .u64 t; cvta.to.shared.u64 t, %1; cvt.u32.u64 %0, t; }" : "=r"(a) : "l"(p));
    return a;
}
__device__ __forceinline__ void cpasync16(uint32_t dst, const void* src) {
    asm volatile("cp.async.cg.shared.global [%0], [%1], 16;"
                 :: "r"(dst), "l"(__cvta_generic_to_global(src)));
}
#define CP_COMMIT() asm volatile("cp.async.commit_group;" ::: "memory")

__device__ __forceinline__ void ldsm_x4(uint32_t& r0, uint32_t& r1, uint32_t& r2, uint32_t& r3,
                                        uint32_t addr) {
    asm volatile("ldmatrix.sync.aligned.m8n8.x4.shared.b16 {%0,%1,%2,%3}, [%4];"
                 : "=r"(r0), "=r"(r1), "=r"(r2), "=r"(r3) : "r"(addr));
}
__device__ __forceinline__ void mma_f16(float* c, const uint32_t* a, uint32_t b0, uint32_t b1) {
    asm volatile("mma.sync.aligned.m16n8k16.row.col.f32.f16.f16.f32 "
                 "{%0,%1,%2,%3}, {%4,%5,%6,%7}, {%8,%9}, {%0,%1,%2,%3};"
                 : "+f"(c[0]), "+f"(c[1]), "+f"(c[2]), "+f"(c[3])
                 : "r"(a[0]), "r"(a[1]), "r"(a[2]), "r"(a[3]), "r"(b0), "r"(b1));
}

// ---------------------------------------------------------------------------
__global__ void sort_rows(const int* __restrict__ sl1, const int* __restrict__ sl2) {
    __shared__ int cnt[64];
    __shared__ int off[64];
    int tid = threadIdx.x;
    if (tid < 64) cnt[tid] = 0;
    if (tid < NT * 8) ((int*)g_flag)[tid] = 0;     // zero dependency flags
    __syncthreads();
    int sl = (tid < NB) ? sl1[tid] : sl2[tid - NB];
    atomicAdd(&cnt[sl], 1);
    __syncthreads();
    if (tid == 0) {
        int acc = 0;
        for (int s = 60; s >= 1; s--) { off[s] = acc; acc += cnt[s]; }
    }
    __syncthreads();
    int pos = atomicAdd(&off[sl], 1);
    g_perm[pos] = tid;
    g_pos[tid]  = pos;
    g_slp[pos]  = sl;
    __syncthreads();
    if (tid < NT) {
        int m = 0;
        for (int s = tid + 1; s <= 60; s++) m += cnt[s];
        g_Mt[tid] = m;
    }
}

// ---------------------------------------------------------------------------
// B' build: k in [0,512) from Wh, k in [512,832) from Wx (k<300 real),
// gate-interleaved N, fp16.
// ---------------------------------------------------------------------------
__global__ void build_B(const float* __restrict__ Wh, const float* __restrict__ Wx) {
    int idx = blockIdx.x * 256 + threadIdx.x;
    if (idx >= NG * KB) return;
    int k = idx / NG;
    int n = idx % NG;
    int nsrc = (n & 3) * 512 + (n >> 2);
    float v;
    if (k < KH)            v = Wh[(size_t)k * NG + nsrc];
    else if (k < KH + NE)  v = Wx[(size_t)(k - KH) * NG + nsrc];
    else                   v = 0.0f;
    g_B[(size_t)n * KB + k] = __float2half_rn(v);
}

// ---------------------------------------------------------------------------
// Gathered x (fp16) per (t, sorted pos), skip inactive
// ---------------------------------------------------------------------------
__global__ void build_Ax(const int* __restrict__ in1, const int* __restrict__ in2,
                         const float* __restrict__ emb) {
    int w = blockIdx.x * 8 + (threadIdx.x >> 5);
    int lane = threadIdx.x & 31;
    if (w >= NT * NB2) return;
    int t   = w >> 10;
    int pos = w & 1023;
    if (pos >= g_Mt[t]) return;
    int b2 = g_perm[pos];
    int tok = (b2 < NB) ? in1[b2 * NT + t] : in2[(b2 - NB) * NT + t];
    const float* er = emb + (size_t)tok * NE;
    size_t base = (size_t)w * KX;
    for (int k = lane; k < KX; k += 32) {
        float v = (k < NE) ? er[k] : 0.0f;
        g_Ax[base + k] = __float2half_rn(v);
    }
}

// ---------------------------------------------------------------------------
// ALL recurrence steps in ONE launch. Grid (32, 8, 60), z = timestep (blocks
// dispatched in z-major-last order => step t fully precedes step t+1).
// Cross-step dependency: flag[t][rt] counts the 32 col-CTAs of (t, rt).
// Chunk order x-first so the prologue overlaps the dependency spin.
// ---------------------------------------------------------------------------
__global__ void __launch_bounds__(256, 3)
lstm_chain(const float* __restrict__ bias) {
    extern __shared__ char dsm[];
    float* zt = (float*)dsm;
    __shared__ float s_bias[64];

    const int tid  = threadIdx.x;
    const int wid  = tid >> 5;
    const int lane = tid & 31;
    const int t  = blockIdx.z;
    const int rt = blockIdx.y, ct = blockIdx.x;
    const int row0 = rt * 128, col0 = ct * 64;
    const bool active = (row0 < g_Mt[t]);
    const int wm0 = (wid & 3) * 32, wn0 = (wid >> 2) * 32;
    const uint32_t sm = smem_u32(dsm);
    const int gid = lane >> 2, tig = lane & 3;

    if (active) {
        if (tid < 64) {
            int u = ct * 16 + (tid >> 2), g = tid & 3;
            s_bias[tid] = bias[g * 512 + u] + ((g == 2) ? 1.0f : 0.0f);
        }

        float acc[2][4][4];
        #pragma unroll
        for (int i = 0; i < 2; i++)
            #pragma unroll
            for (int j = 0; j < 4; j++)
                #pragma unroll
                for (int k = 0; k < 4; k++) acc[i][j][k] = 0.0f;

        {
            const int NCe = (t > 0) ? NCALL : 5;   // t=0: x-only
            const __half* aH = g_Abuf[t & 1] + (size_t)row0 * KH;
            const __half* aX = g_Ax + ((size_t)t * NB2 + row0) * KX;
            const __half* bRow = g_B + (size_t)col0 * KB;

            // chunk map: x chunks (8..12) first, then h chunks (0..7)
            auto load_chunk = [&](int ci, int st) {
                int c = (t > 0) ? ((ci < 5) ? (8 + ci) : (ci - 5)) : (8 + ci);
                uint32_t aB = sm + st * STAGE_BYTES;
                uint32_t bB = aB + 16384;
                const __half* bS = bRow + c * 64;
                #pragma unroll
                for (int i = 0; i < 2; i++) {
                    int idx = i * 256 + tid;
                    int n = idx >> 3, s = idx & 7;
                    cpasync16(bB + SWZ(n * 128 + s * 16), bS + (size_t)n * KB + s * 8);
                }
                const __half* aS;
                int stride;
                if (c < 8) { aS = aH + c * 64;       stride = KH; }
                else       { aS = aX + (c - 8) * 64; stride = KX; }
                #pragma unroll
                for (int i = 0; i < 4; i++) {
                    int idx = i * 256 + tid;
                    int r = idx >> 3, s = idx & 7;
                    cpasync16(aB + SWZ(r * 128 + s * 16), aS + (size_t)r * stride + s * 8);
                }
            };

            // prologue: first 3 chunks are x (no dependency)
            for (int s = 0; s < STAGES && s < NCe; s++) { load_chunk(s, s); CP_COMMIT(); }

            // wait for previous step's row-tile (overlaps with x loads in flight)
            if (t > 0) {
                if (tid == 0) {
                    volatile int* f = &g_flag[t - 1][rt];
                    while (*f < 32) __nanosleep(64);
                }
                __syncthreads();
                __threadfence();
            }

            const int a_row = wm0 + (lane & 15);
            const int a_colb = 16 * (lane >> 4);
            const int b_row = wn0 + lane;
            for (int ci = 0; ci < NCe; ci++) {
                int st = ci % STAGES;
                int rem = NCe - 1 - ci;
                if (rem >= 2)      asm volatile("cp.async.wait_group 2;" ::: "memory");
                else if (rem == 1) asm volatile("cp.async.wait_group 1;" ::: "memory");
                else               asm volatile("cp.async.wait_group 0;" ::: "memory");
                __syncthreads();

                uint32_t aB = sm + st * STAGE_BYTES;
                uint32_t bB = aB + 16384;
                #pragma unroll
                for (int kk = 0; kk < 4; kk++) {
                    uint32_t a[2][4];
                    #pragma unroll
                    for (int mf = 0; mf < 2; mf++) {
                        uint32_t addr = aB + SWZ((a_row + mf * 16) * 128 + kk * 32 + a_colb);
                        ldsm_x4(a[mf][0], a[mf][1], a[mf][2], a[mf][3], addr);
                    }
                    uint32_t blo[4], bhi[4];
                    uint32_t addr0 = bB + SWZ(b_row * 128 + kk * 32);
                    ldsm_x4(blo[0], blo[1], blo[2], blo[3], addr0);
                    uint32_t addr1 = bB + SWZ(b_row * 128 + kk * 32 + 16);
                    ldsm_x4(bhi[0], bhi[1], bhi[2], bhi[3], addr1);
                    #pragma unroll
                    for (int mf = 0; mf < 2; mf++)
                        #pragma unroll
                        for (int nf = 0; nf < 4; nf++)
                            mma_f16(acc[mf][nf], a[mf], blo[nf], bhi[nf]);
                }
                __syncthreads();
                if (ci + STAGES < NCe) { load_chunk(ci + STAGES, st); CP_COMMIT(); }
            }
        }
        __syncthreads();   // all MMA smem reads done before z overwrite

        #pragma unroll
        for (int mf = 0; mf < 2; mf++)
            #pragma unroll
            for (int nf = 0; nf < 4; nf++) {
                int r = wm0 + mf * 16 + gid;
                int cc = wn0 + nf * 8 + tig * 2;
                *reinterpret_cast<float2*>(&zt[r * ZS + cc]) =
                    make_float2(acc[mf][nf][0], acc[mf][nf][1]);
                *reinterpret_cast<float2*>(&zt[(r + 8) * ZS + cc]) =
                    make_float2(acc[mf][nf][2], acc[mf][nf][3]);
            }
        __syncthreads();

        // fused LSTM cell: 2 threads per row, 8 units each, coalesced float4 I/O
        {
            int row = tid >> 1;
            int ul0 = (tid & 1) * 8;
            size_t b = (size_t)row0 + row;
            bool valid = t < g_slp[b];
            float cold[8], hnew[8];
            float* hp = g_h + b * NH + ct * 16 + ul0;
            float* cp = g_c + b * NH + ct * 16 + ul0;
            if (t > 0) {
                #pragma unroll
                for (int q = 0; q < 2; q++)
                    *reinterpret_cast<float4*>(&cold[4 * q]) = *reinterpret_cast<const float4*>(cp + 4 * q);
            } else {
                #pragma unroll
                for (int i = 0; i < 8; i++) cold[i] = 0.0f;
            }
            #pragma unroll
            for (int i = 0; i < 8; i++) {
                float4 z4 = *reinterpret_cast<const float4*>(&zt[row * ZS + (ul0 + i) * 4]);
                float4 b4 = *reinterpret_cast<const float4*>(&s_bias[(ul0 + i) * 4]);
                float zi = z4.x + b4.x;
                float zj = z4.y + b4.y;
                float zf = z4.z + b4.z;
                float zo = z4.w + b4.w;
                float nc = cold[i] * sigmf(zf) + sigmf(zi) * tanh_fast(zj);
                float nh = tanh_fast(nc) * sigmf(zo);
                cold[i] = nc; hnew[i] = nh;
            }
            if (valid) {
                #pragma unroll
                for (int q = 0; q < 2; q++) {
                    *reinterpret_cast<float4*>(cp + 4 * q) = *reinterpret_cast<float4*>(&cold[4 * q]);
                    *reinterpret_cast<float4*>(hp + 4 * q) = *reinterpret_cast<float4*>(&hnew[4 * q]);
                }
                __half* an = g_Abuf[(t + 1) & 1] + b * KH + ct * 16 + ul0;
                #pragma unroll
                for (int i = 0; i < 4; i++) {
                    __half2 hh;
                    hh.x = __float2half_rn(hnew[2 * i]);
                    hh.y = __float2half_rn(hnew[2 * i + 1]);
                    *reinterpret_cast<__half2*>(an + 2 * i) = hh;
                }
            }
        }
        __threadfence();   // make this CTA's writes visible before arrival
    }

    // arrive on this step's flag (active or not)
    __syncthreads();
    if (tid == 0 && t < NT - 1) atomicAdd(&g_flag[t][rt], 1);
}

// ---------------------------------------------------------------------------
__global__ void gemm128(const float* __restrict__ A, int lda,
                        const float* __restrict__ Bm, int ldb,
                        float* __restrict__ C, int ldc,
                        int K, const float* __restrict__ aux) {
    __shared__ float As[8][128];
    __shared__ float Bs[8][128];
    const int tid  = threadIdx.x;
    const int row0 = blockIdx.y * 128;
    const int col0 = blockIdx.x * 128;
    float acc[8][8];
    #pragma unroll
    for (int i = 0; i < 8; i++)
        #pragma unroll
        for (int j = 0; j < 8; j++) acc[i][j] = 0.0f;
    const int tr = (tid >> 4) << 3;
    const int tc = (tid & 15) << 3;
    for (int k0 = 0; k0 < K; k0 += 8) {
        #pragma unroll
        for (int i = 0; i < 4; i++) {
            int p = tid * 4 + i, ar = p >> 3, ak = p & 7;
            As[ak][ar] = (k0 + ak < K) ? A[(size_t)(row0 + ar) * lda + k0 + ak] : 0.0f;
        }
        #pragma unroll
        for (int i = 0; i < 4; i++) {
            int p = tid * 4 + i, bk = p >> 7, bc = p & 127;
            Bs[bk][bc] = (k0 + bk < K) ? Bm[(size_t)(k0 + bk) * ldb + col0 + bc] : 0.0f;
        }
        __syncthreads();
        #pragma unroll
        for (int kk = 0; kk < 8; kk++) {
            float ra[8], rb[8];
            #pragma unroll
            for (int i = 0; i < 8; i++) ra[i] = As[kk][tr + i];
            #pragma unroll
            for (int j = 0; j < 8; j++) rb[j] = Bs[kk][tc + j];
            #pragma unroll
            for (int i = 0; i < 8; i++)
                #pragma unroll
                for (int j = 0; j < 8; j++) acc[i][j] += ra[i] * rb[j];
        }
        __syncthreads();
    }
    #pragma unroll
    for (int i = 0; i < 8; i++)
        #pragma unroll
        for (int j = 0; j < 8; j++) {
            size_t idx = (size_t)(row0 + tr + i) * ldc + (col0 + tc + j);
            float v = acc[i][j] + aux[col0 + tc + j];
            C[idx] = v > 0.0f ? v : 0.0f;
        }
}

// ---------------------------------------------------------------------------
__global__ void combine(const int* __restrict__ sl1, const int* __restrict__ sl2) {
    int b = blockIdx.x;
    __shared__ float red[256];
    float len1 = (float)sl1[b] / (float)NT;
    float len2 = (float)sl2[b] / (float)NT;
    int p1 = g_pos[b], p2 = g_pos[NB + b];
    float lsum = 0.0f;
    float* hc = g_hc + (size_t)b * NHC;
    for (int k = threadIdx.x; k < NH + 1; k += 256) {
        float a = (k < NH) ? g_h[(size_t)p1 * NH + k] : len1;
        float d = (k < NH) ? g_h[(size_t)p2 * NH + k] : len2;
        float s = a - d;
        hc[k]        = a;
        hc[513 + k]  = d;
        hc[1026 + k] = s;
        hc[1540 + k] = a * d;
        lsum += s * s;
    }
    red[threadIdx.x] = lsum;
    __syncthreads();
    for (int s = 128; s > 0; s >>= 1) {
        if (threadIdx.x < s) red[threadIdx.x] += red[threadIdx.x + s];
        __syncthreads();
    }
    if (threadIdx.x == 0) hc[1539] = red[0];
}

__global__ void final_out(const float* __restrict__ W2, const float* __restrict__ b2,
                          float* __restrict__ out) {
    int b = blockIdx.x;
    __shared__ float s0[64], s1[64];
    float a0 = 0.0f, a1 = 0.0f;
    for (int k = threadIdx.x; k < NM; k += 64) {
        float e = g_e1[(size_t)b * NM + k];
        a0 += e * W2[k * 2 + 0];
        a1 += e * W2[k * 2 + 1];
    }
    s0[threadIdx.x] = a0;
    s1[threadIdx.x] = a1;
    __syncthreads();
    for (int s = 32; s > 0; s >>= 1) {
        if (threadIdx.x < s) { s0[threadIdx.x] += s0[threadIdx.x + s];
                               s1[threadIdx.x] += s1[threadIdx.x + s]; }
        __syncthreads();
    }
    if (threadIdx.x == 0) {
        out[b * 2 + 0] = s0[0] + b2[0];
        out[b * 2 + 1] = s1[0] + b2[1];
    }
}

// ---------------------------------------------------------------------------
extern "C" void kernel_launch(void* const* d_in, const int* in_sizes, int n_in,
                              void* d_out, int out_size) {
    const int*   in1 = (const int*)  d_in[0];
    const int*   in2 = (const int*)  d_in[1];
    const int*   sl1 = (const int*)  d_in[2];
    const int*   sl2 = (const int*)  d_in[3];
    const float* emb = (const float*)d_in[4];
    const float* lk  = (const float*)d_in[5];
    const float* lb  = (const float*)d_in[6];
    const float* W1  = (const float*)d_in[7];
    const float* b1  = (const float*)d_in[8];
    const float* W2  = (const float*)d_in[9];
    const float* b2  = (const float*)d_in[10];
    float* out = (float*)d_out;

    float *p_hc, *p_e1;
    cudaGetSymbolAddress((void**)&p_hc, g_hc);
    cudaGetSymbolAddress((void**)&p_e1, g_e1);

    cudaFuncSetAttribute(lstm_chain, cudaFuncAttributeMaxDynamicSharedMemorySize, GEMM_SMEM);

    const float* Wh = lk + (size_t)NE * NG;   // rows [300, 812)
    const float* Wx = lk;                     // rows [0, 300)

    sort_rows<<<1, NB2>>>(sl1, sl2);
    build_B<<<(NG * KB + 255) / 256, 256>>>(Wh, Wx);
    build_Ax<<<(NT * NB2 + 7) / 8, 256>>>(in1, in2, emb);

    // entire recurrence: one launch, flag-chained across steps
    lstm_chain<<<dim3(32, 8, NT), 256, GEMM_SMEM>>>(lb);

    combine<<<NB, 256>>>(sl1, sl2);
    gemm128<<<dim3(NM / 128, NB / 128), 256>>>(p_hc, NHC, W1, NM, p_e1, NM, NHC, b1);
    final_out<<<NB, 64>>>(W2, b2, out);
}

// round 16
// speedup vs baseline: 1.0624x; 1.0624x over previous
#include <cuda_runtime.h>
#include <cuda_fp16.h>
#include <math.h>
#include <stdint.h>

#define NB   512
#define NE   300
#define NH   512
#define NM   256
#define NB2  1024
#define NG   2048
#define NHC  2053
#define NT   60

#define KH   512           // h part of K
#define KX   320           // x part of K (300 padded)
#define KB   832           // total B' K
#define NCALL 13           // 13 chunks of 64

#define STAGES 3
#define STAGE_BYTES 24576  // 16KB A + 8KB B
#define GEMM_SMEM (STAGES*STAGE_BYTES)
#define ZS 72              // z-tile row stride (floats), 128x64 tile

__device__ float g_h [NB2 * NH];                   // sorted row order
__device__ float g_c [NB2 * NH];
__device__ float g_hc[NB * NHC];
__device__ float g_e1[NB * NM];
__device__ __half g_Abuf[2][(size_t)NB2 * KH];     // ping-pong h (fp16)
__device__ __half g_B  [(size_t)NG * KB];          // [Wh|Wx] fp16, gate-interleaved N
__device__ __half g_Ax [(size_t)NT * NB2 * KX];    // emb fp16, sorted rows
__device__ int g_perm[NB2];
__device__ int g_pos [NB2];
__device__ int g_slp [NB2];
__device__ int g_Mt  [NT];
__device__ int g_flag[NT][8][8];                   // (step, row-tile, col-group) count to 4

__device__ __forceinline__ float sigmf(float x) {
    return __fdividef(1.0f, 1.0f + __expf(-x));
}
__device__ __forceinline__ float tanh_fast(float x) {
    float xx = fminf(fmaxf(x, -15.0f), 15.0f);
    float e = __expf(2.0f * xx);
    return __fdividef(e - 1.0f, e + 1.0f);
}

#define SWZ(b) ((b) ^ (((b) >> 3) & 0x70))

__device__ __forceinline__ uint32_t smem_u32(const void* p) {
    uint32_t a;
    asm("{ .reg .u64 t; cvta.to.shared.u64 t, %1; cvt.u32.u64 %0, t; }" : "=r"(a) : "l"(p));
    return a;
}
__device__ __forceinline__ void cpasync16(uint32_t dst, const void* src) {
    asm volatile("cp.async.cg.shared.global [%0], [%1], 16;"
                 :: "r"(dst), "l"(__cvta_generic_to_global(src)));
}
#define CP_COMMIT() asm volatile("cp.async.commit_group;" ::: "memory")

__device__ __forceinline__ void ldsm_x4(uint32_t& r0, uint32_t& r1, uint32_t& r2, uint32_t& r3,
                                        uint32_t addr) {
    asm volatile("ldmatrix.sync.aligned.m8n8.x4.shared.b16 {%0,%1,%2,%3}, [%4];"
                 : "=r"(r0), "=r"(r1), "=r"(r2), "=r"(r3) : "r"(addr));
}
__device__ __forceinline__ void mma_f16(float* c, const uint32_t* a, uint32_t b0, uint32_t b1) {
    asm volatile("mma.sync.aligned.m16n8k16.row.col.f32.f16.f16.f32 "
                 "{%0,%1,%2,%3}, {%4,%5,%6,%7}, {%8,%9}, {%0,%1,%2,%3};"
                 : "+f"(c[0]), "+f"(c[1]), "+f"(c[2]), "+f"(c[3])
                 : "r"(a[0]), "r"(a[1]), "r"(a[2]), "r"(a[3]), "r"(b0), "r"(b1));
}

// ---------------------------------------------------------------------------
__global__ void sort_rows(const int* __restrict__ sl1, const int* __restrict__ sl2) {
    __shared__ int cnt[64];
    __shared__ int off[64];
    int tid = threadIdx.x;
    if (tid < 64) cnt[tid] = 0;
    for (int i = tid; i < NT * 64; i += NB2) ((int*)g_flag)[i] = 0;  // zero flags
    __syncthreads();
    int sl = (tid < NB) ? sl1[tid] : sl2[tid - NB];
    atomicAdd(&cnt[sl], 1);
    __syncthreads();
    if (tid == 0) {
        int acc = 0;
        for (int s = 60; s >= 1; s--) { off[s] = acc; acc += cnt[s]; }
    }
    __syncthreads();
    int pos = atomicAdd(&off[sl], 1);
    g_perm[pos] = tid;
    g_pos[tid]  = pos;
    g_slp[pos]  = sl;
    __syncthreads();
    if (tid < NT) {
        int m = 0;
        for (int s = tid + 1; s <= 60; s++) m += cnt[s];
        g_Mt[tid] = m;
    }
}

// ---------------------------------------------------------------------------
__global__ void build_B(const float* __restrict__ Wh, const float* __restrict__ Wx) {
    int idx = blockIdx.x * 256 + threadIdx.x;
    if (idx >= NG * KB) return;
    int k = idx / NG;
    int n = idx % NG;
    int nsrc = (n & 3) * 512 + (n >> 2);
    float v;
    if (k < KH)            v = Wh[(size_t)k * NG + nsrc];
    else if (k < KH + NE)  v = Wx[(size_t)(k - KH) * NG + nsrc];
    else                   v = 0.0f;
    g_B[(size_t)n * KB + k] = __float2half_rn(v);
}

// ---------------------------------------------------------------------------
__global__ void build_Ax(const int* __restrict__ in1, const int* __restrict__ in2,
                         const float* __restrict__ emb) {
    int w = blockIdx.x * 8 + (threadIdx.x >> 5);
    int lane = threadIdx.x & 31;
    if (w >= NT * NB2) return;
    int t   = w >> 10;
    int pos = w & 1023;
    if (pos >= g_Mt[t]) return;
    int b2 = g_perm[pos];
    int tok = (b2 < NB) ? in1[b2 * NT + t] : in2[(b2 - NB) * NT + t];
    const float* er = emb + (size_t)tok * NE;
    size_t base = (size_t)w * KX;
    for (int k = lane; k < KX; k += 32) {
        float v = (k < NE) ? er[k] : 0.0f;
        g_Ax[base + k] = __float2half_rn(v);
    }
}

// ---------------------------------------------------------------------------
// ALL recurrence steps in ONE launch. Grid (32, 8, 60), z = timestep.
// Fine-grained dependency: h chunk c of (t, rt) needs only producer col-CTAs
// 4c..4c+3 of (t-1, rt): flag[t-1][rt][c] == 4. x chunks load first.
// ---------------------------------------------------------------------------
__global__ void __launch_bounds__(256, 3)
lstm_chain(const float* __restrict__ bias) {
    extern __shared__ char dsm[];
    float* zt = (float*)dsm;
    __shared__ float s_bias[64];

    const int tid  = threadIdx.x;
    const int wid  = tid >> 5;
    const int lane = tid & 31;
    const int t  = blockIdx.z;
    const int rt = blockIdx.y, ct = blockIdx.x;
    const int row0 = rt * 128, col0 = ct * 64;
    const bool active = (row0 < g_Mt[t]);
    const int wm0 = (wid & 3) * 32, wn0 = (wid >> 2) * 32;
    const uint32_t sm = smem_u32(dsm);
    const int gid = lane >> 2, tig = lane & 3;

    if (active) {
        if (tid < 64) {
            int u = ct * 16 + (tid >> 2), g = tid & 3;
            s_bias[tid] = bias[g * 512 + u] + ((g == 2) ? 1.0f : 0.0f);
        }

        float acc[2][4][4];
        #pragma unroll
        for (int i = 0; i < 2; i++)
            #pragma unroll
            for (int j = 0; j < 4; j++)
                #pragma unroll
                for (int k = 0; k < 4; k++) acc[i][j][k] = 0.0f;

        {
            const int NCe = (t > 0) ? NCALL : 5;   // t=0: x-only
            const __half* aH = g_Abuf[t & 1] + (size_t)row0 * KH;
            const __half* aX = g_Ax + ((size_t)t * NB2 + row0) * KX;
            const __half* bRow = g_B + (size_t)col0 * KB;

            // consumer chunk order: x chunks (8..12) first, then h chunks (0..7)
            auto chunk_of = [&](int ci) { return (ci < 5) ? (8 + ci) : (ci - 5); };

            // wait until group for h chunk c is fully produced (4 arrivals)
            auto wait_group = [&](int ci) {
                if (t == 0 || ci < 5) return;
                int c = ci - 5;
                if (tid == 0) {
                    volatile int* f = &g_flag[t - 1][rt][c];
                    while (*f < 4) __nanosleep(32);
                }
                __syncthreads();
            };

            auto load_chunk = [&](int ci, int st) {
                int c = chunk_of(ci);
                uint32_t aB = sm + st * STAGE_BYTES;
                uint32_t bB = aB + 16384;
                const __half* bS = bRow + c * 64;
                #pragma unroll
                for (int i = 0; i < 2; i++) {
                    int idx = i * 256 + tid;
                    int n = idx >> 3, s = idx & 7;
                    cpasync16(bB + SWZ(n * 128 + s * 16), bS + (size_t)n * KB + s * 8);
                }
                const __half* aS;
                int stride;
                if (c < 8) { aS = aH + c * 64;       stride = KH; }
                else       { aS = aX + (c - 8) * 64; stride = KX; }
                #pragma unroll
                for (int i = 0; i < 4; i++) {
                    int idx = i * 256 + tid;
                    int r = idx >> 3, s = idx & 7;
                    cpasync16(aB + SWZ(r * 128 + s * 16), aS + (size_t)r * stride + s * 8);
                }
            };

            // prologue: first 3 chunks are x (no dependency)
            for (int s = 0; s < STAGES && s < NCe; s++) { load_chunk(s, s); CP_COMMIT(); }

            const int a_row = wm0 + (lane & 15);
            const int a_colb = 16 * (lane >> 4);
            const int b_row = wn0 + lane;
            for (int ci = 0; ci < NCe; ci++) {
                int st = ci % STAGES;
                int rem = NCe - 1 - ci;
                if (rem >= 2)      asm volatile("cp.async.wait_group 2;" ::: "memory");
                else if (rem == 1) asm volatile("cp.async.wait_group 1;" ::: "memory");
                else               asm volatile("cp.async.wait_group 0;" ::: "memory");
                __syncthreads();

                uint32_t aB = sm + st * STAGE_BYTES;
                uint32_t bB = aB + 16384;
                #pragma unroll
                for (int kk = 0; kk < 4; kk++) {
                    uint32_t a[2][4];
                    #pragma unroll
                    for (int mf = 0; mf < 2; mf++) {
                        uint32_t addr = aB + SWZ((a_row + mf * 16) * 128 + kk * 32 + a_colb);
                        ldsm_x4(a[mf][0], a[mf][1], a[mf][2], a[mf][3], addr);
                    }
                    uint32_t blo[4], bhi[4];
                    uint32_t addr0 = bB + SWZ(b_row * 128 + kk * 32);
                    ldsm_x4(blo[0], blo[1], blo[2], blo[3], addr0);
                    uint32_t addr1 = bB + SWZ(b_row * 128 + kk * 32 + 16);
                    ldsm_x4(bhi[0], bhi[1], bhi[2], bhi[3], addr1);
                    #pragma unroll
                    for (int mf = 0; mf < 2; mf++)
                        #pragma unroll
                        for (int nf = 0; nf < 4; nf++)
                            mma_f16(acc[mf][nf], a[mf], blo[nf], bhi[nf]);
                }
                __syncthreads();
                if (ci + STAGES < NCe) {
                    wait_group(ci + STAGES);
                    load_chunk(ci + STAGES, st);
                    CP_COMMIT();
                }
            }
        }
        __syncthreads();   // all MMA smem reads done before z overwrite

        #pragma unroll
        for (int mf = 0; mf < 2; mf++)
            #pragma unroll
            for (int nf = 0; nf < 4; nf++) {
                int r = wm0 + mf * 16 + gid;
                int cc = wn0 + nf * 8 + tig * 2;
                *reinterpret_cast<float2*>(&zt[r * ZS + cc]) =
                    make_float2(acc[mf][nf][0], acc[mf][nf][1]);
                *reinterpret_cast<float2*>(&zt[(r + 8) * ZS + cc]) =
                    make_float2(acc[mf][nf][2], acc[mf][nf][3]);
            }
        __syncthreads();

        // fused LSTM cell: 2 threads per row, 8 units each, coalesced float4 I/O
        {
            int row = tid >> 1;
            int ul0 = (tid & 1) * 8;
            size_t b = (size_t)row0 + row;
            bool valid = t < g_slp[b];
            float cold[8], hnew[8];
            float* hp = g_h + b * NH + ct * 16 + ul0;
            float* cp = g_c + b * NH + ct * 16 + ul0;
            if (t > 0) {
                #pragma unroll
                for (int q = 0; q < 2; q++)
                    *reinterpret_cast<float4*>(&cold[4 * q]) = *reinterpret_cast<const float4*>(cp + 4 * q);
            } else {
                #pragma unroll
                for (int i = 0; i < 8; i++) cold[i] = 0.0f;
            }
            #pragma unroll
            for (int i = 0; i < 8; i++) {
                float4 z4 = *reinterpret_cast<const float4*>(&zt[row * ZS + (ul0 + i) * 4]);
                float4 b4 = *reinterpret_cast<const float4*>(&s_bias[(ul0 + i) * 4]);
                float zi = z4.x + b4.x;
                float zj = z4.y + b4.y;
                float zf = z4.z + b4.z;
                float zo = z4.w + b4.w;
                float nc = cold[i] * sigmf(zf) + sigmf(zi) * tanh_fast(zj);
                float nh = tanh_fast(nc) * sigmf(zo);
                cold[i] = nc; hnew[i] = nh;
            }
            if (valid) {
                #pragma unroll
                for (int q = 0; q < 2; q++) {
                    *reinterpret_cast<float4*>(cp + 4 * q) = *reinterpret_cast<float4*>(&cold[4 * q]);
                    *reinterpret_cast<float4*>(hp + 4 * q) = *reinterpret_cast<float4*>(&hnew[4 * q]);
                }
                __half* an = g_Abuf[(t + 1) & 1] + b * KH + ct * 16 + ul0;
                #pragma unroll
                for (int i = 0; i < 4; i++) {
                    __half2 hh;
                    hh.x = __float2half_rn(hnew[2 * i]);
                    hh.y = __float2half_rn(hnew[2 * i + 1]);
                    *reinterpret_cast<__half2*>(an + 2 * i) = hh;
                }
            }
        }
        __threadfence();   // make this CTA's writes visible before arrival
    }

    // arrive on this step's group flag (active or not)
    __syncthreads();
    if (tid == 0 && t < NT - 1) atomicAdd(&g_flag[t][rt][ct >> 2], 1);
}

// ---------------------------------------------------------------------------
__global__ void gemm128(const float* __restrict__ A, int lda,
                        const float* __restrict__ Bm, int ldb,
                        float* __restrict__ C, int ldc,
                        int K, const float* __restrict__ aux) {
    __shared__ float As[8][128];
    __shared__ float Bs[8][128];
    const int tid  = threadIdx.x;
    const int row0 = blockIdx.y * 128;
    const int col0 = blockIdx.x * 128;
    float acc[8][8];
    #pragma unroll
    for (int i = 0; i < 8; i++)
        #pragma unroll
        for (int j = 0; j < 8; j++) acc[i][j] = 0.0f;
    const int tr = (tid >> 4) << 3;
    const int tc = (tid & 15) << 3;
    for (int k0 = 0; k0 < K; k0 += 8) {
        #pragma unroll
        for (int i = 0; i < 4; i++) {
            int p = tid * 4 + i, ar = p >> 3, ak = p & 7;
            As[ak][ar] = (k0 + ak < K) ? A[(size_t)(row0 + ar) * lda + k0 + ak] : 0.0f;
        }
        #pragma unroll
        for (int i = 0; i < 4; i++) {
            int p = tid * 4 + i, bk = p >> 7, bc = p & 127;
            Bs[bk][bc] = (k0 + bk < K) ? Bm[(size_t)(k0 + bk) * ldb + col0 + bc] : 0.0f;
        }
        __syncthreads();
        #pragma unroll
        for (int kk = 0; kk < 8; kk++) {
            float ra[8], rb[8];
            #pragma unroll
            for (int i = 0; i < 8; i++) ra[i] = As[kk][tr + i];
            #pragma unroll
            for (int j = 0; j < 8; j++) rb[j] = Bs[kk][tc + j];
            #pragma unroll
            for (int i = 0; i < 8; i++)
                #pragma unroll
                for (int j = 0; j < 8; j++) acc[i][j] += ra[i] * rb[j];
        }
        __syncthreads();
    }
    #pragma unroll
    for (int i = 0; i < 8; i++)
        #pragma unroll
        for (int j = 0; j < 8; j++) {
            size_t idx = (size_t)(row0 + tr + i) * ldc + (col0 + tc + j);
            float v = acc[i][j] + aux[col0 + tc + j];
            C[idx] = v > 0.0f ? v : 0.0f;
        }
}

// ---------------------------------------------------------------------------
__global__ void combine(const int* __restrict__ sl1, const int* __restrict__ sl2) {
    int b = blockIdx.x;
    __shared__ float red[256];
    float len1 = (float)sl1[b] / (float)NT;
    float len2 = (float)sl2[b] / (float)NT;
    int p1 = g_pos[b], p2 = g_pos[NB + b];
    float lsum = 0.0f;
    float* hc = g_hc + (size_t)b * NHC;
    for (int k = threadIdx.x; k < NH + 1; k += 256) {
        float a = (k < NH) ? g_h[(size_t)p1 * NH + k] : len1;
        float d = (k < NH) ? g_h[(size_t)p2 * NH + k] : len2;
        float s = a - d;
        hc[k]        = a;
        hc[513 + k]  = d;
        hc[1026 + k] = s;
        hc[1540 + k] = a * d;
        lsum += s * s;
    }
    red[threadIdx.x] = lsum;
    __syncthreads();
    for (int s = 128; s > 0; s >>= 1) {
        if (threadIdx.x < s) red[threadIdx.x] += red[threadIdx.x + s];
        __syncthreads();
    }
    if (threadIdx.x == 0) hc[1539] = red[0];
}

__global__ void final_out(const float* __restrict__ W2, const float* __restrict__ b2,
                          float* __restrict__ out) {
    int b = blockIdx.x;
    __shared__ float s0[64], s1[64];
    float a0 = 0.0f, a1 = 0.0f;
    for (int k = threadIdx.x; k < NM; k += 64) {
        float e = g_e1[(size_t)b * NM + k];
        a0 += e * W2[k * 2 + 0];
        a1 += e * W2[k * 2 + 1];
    }
    s0[threadIdx.x] = a0;
    s1[threadIdx.x] = a1;
    __syncthreads();
    for (int s = 32; s > 0; s >>= 1) {
        if (threadIdx.x < s) { s0[threadIdx.x] += s0[threadIdx.x + s];
                               s1[threadIdx.x] += s1[threadIdx.x + s]; }
        __syncthreads();
    }
    if (threadIdx.x == 0) {
        out[b * 2 + 0] = s0[0] + b2[0];
        out[b * 2 + 1] = s1[0] + b2[1];
    }
}

// ---------------------------------------------------------------------------
extern "C" void kernel_launch(void* const* d_in, const int* in_sizes, int n_in,
                              void* d_out, int out_size) {
    const int*   in1 = (const int*)  d_in[0];
    const int*   in2 = (const int*)  d_in[1];
    const int*   sl1 = (const int*)  d_in[2];
    const int*   sl2 = (const int*)  d_in[3];
    const float* emb = (const float*)d_in[4];
    const float* lk  = (const float*)d_in[5];
    const float* lb  = (const float*)d_in[6];
    const float* W1  = (const float*)d_in[7];
    const float* b1  = (const float*)d_in[8];
    const float* W2  = (const float*)d_in[9];
    const float* b2  = (const float*)d_in[10];
    float* out = (float*)d_out;

    float *p_hc, *p_e1;
    cudaGetSymbolAddress((void**)&p_hc, g_hc);
    cudaGetSymbolAddress((void**)&p_e1, g_e1);

    cudaFuncSetAttribute(lstm_chain, cudaFuncAttributeMaxDynamicSharedMemorySize, GEMM_SMEM);

    const float* Wh = lk + (size_t)NE * NG;   // rows [300, 812)
    const float* Wx = lk;                     // rows [0, 300)

    sort_rows<<<1, NB2>>>(sl1, sl2);
    build_B<<<(NG * KB + 255) / 256, 256>>>(Wh, Wx);
    build_Ax<<<(NT * NB2 + 7) / 8, 256>>>(in1, in2, emb);

    // entire recurrence: one launch, group-flag-chained across steps
    lstm_chain<<<dim3(32, 8, NT), 256, GEMM_SMEM>>>(lb);

    combine<<<NB, 256>>>(sl1, sl2);
    gemm128<<<dim3(NM / 128, NB / 128), 256>>>(p_hc, NHC, W1, NM, p_e1, NM, NHC, b1);
    final_out<<<NB, 64>>>(W2, b2, out);
}

// round 17
// speedup vs baseline: 1.1518x; 1.0842x over previous
#include <cuda_runtime.h>
#include <cuda_fp16.h>
#include <math.h>
#include <stdint.h>

#define NB   512
#define NE   300
#define NH   512
#define NM   256
#define NB2  1024
#define NG   2048
#define NHC  2053
#define NT   60

#define KH   512           // h part of K
#define KX   320           // x part of K (300 padded)
#define KB   832           // total B' K
#define NCALL 13           // 13 chunks of 64

#define STAGES 4
#define STAGE_BYTES 16384  // 8KB A + 8KB B
#define GEMM_SMEM (STAGES*STAGE_BYTES)
#define ZS 72              // z-tile row stride (floats), 64x64 tile

__device__ float g_h [NB2 * NH];                   // sorted row order
__device__ float g_c [NB2 * NH];
__device__ float g_hc[NB * NHC];
__device__ float g_e1[NB * NM];
__device__ __half g_Abuf[2][(size_t)NB2 * KH];     // ping-pong h (fp16)
__device__ __half g_B  [(size_t)NG * KB];          // [Wh|Wx] fp16, gate-interleaved N
__device__ __half g_Ax [(size_t)NT * NB2 * KX];    // emb fp16, sorted rows
__device__ int g_perm[NB2];
__device__ int g_pos [NB2];
__device__ int g_slp [NB2];
__device__ int g_Mt  [NT];
__device__ int g_flag[NT][16][8];                  // (step, row-tile64, col-group) to 4

__device__ __forceinline__ float sigmf(float x) {
    return __fdividef(1.0f, 1.0f + __expf(-x));
}
__device__ __forceinline__ float tanh_fast(float x) {
    float xx = fminf(fmaxf(x, -15.0f), 15.0f);
    float e = __expf(2.0f * xx);
    return __fdividef(e - 1.0f, e + 1.0f);
}

#define SWZ(b) ((b) ^ (((b) >> 3) & 0x70))

__device__ __forceinline__ uint32_t smem_u32(const void* p) {
    uint32_t a;
    asm("{ .reg .u64 t; cvta.to.shared.u64 t, %1; cvt.u32.u64 %0, t; }" : "=r"(a) : "l"(p));
    return a;
}
__device__ __forceinline__ void cpasync16(uint32_t dst, const void* src) {
    asm volatile("cp.async.cg.shared.global [%0], [%1], 16;"
                 :: "r"(dst), "l"(__cvta_generic_to_global(src)));
}
#define CP_COMMIT() asm volatile("cp.async.commit_group;" ::: "memory")

__device__ __forceinline__ void ldsm_x4(uint32_t& r0, uint32_t& r1, uint32_t& r2, uint32_t& r3,
                                        uint32_t addr) {
    asm volatile("ldmatrix.sync.aligned.m8n8.x4.shared.b16 {%0,%1,%2,%3}, [%4];"
                 : "=r"(r0), "=r"(r1), "=r"(r2), "=r"(r3) : "r"(addr));
}
__device__ __forceinline__ void mma_f16(float* c, const uint32_t* a, uint32_t b0, uint32_t b1) {
    asm volatile("mma.sync.aligned.m16n8k16.row.col.f32.f16.f16.f32 "
                 "{%0,%1,%2,%3}, {%4,%5,%6,%7}, {%8,%9}, {%0,%1,%2,%3};"
                 : "+f"(c[0]), "+f"(c[1]), "+f"(c[2]), "+f"(c[3])
                 : "r"(a[0]), "r"(a[1]), "r"(a[2]), "r"(a[3]), "r"(b0), "r"(b1));
}

// ---------------------------------------------------------------------------
__global__ void sort_rows(const int* __restrict__ sl1, const int* __restrict__ sl2) {
    __shared__ int cnt[64];
    __shared__ int off[64];
    int tid = threadIdx.x;
    if (tid < 64) cnt[tid] = 0;
    for (int i = tid; i < NT * 16 * 8; i += NB2) ((int*)g_flag)[i] = 0;  // zero flags
    __syncthreads();
    int sl = (tid < NB) ? sl1[tid] : sl2[tid - NB];
    atomicAdd(&cnt[sl], 1);
    __syncthreads();
    if (tid == 0) {
        int acc = 0;
        for (int s = 60; s >= 1; s--) { off[s] = acc; acc += cnt[s]; }
    }
    __syncthreads();
    int pos = atomicAdd(&off[sl], 1);
    g_perm[pos] = tid;
    g_pos[tid]  = pos;
    g_slp[pos]  = sl;
    __syncthreads();
    if (tid < NT) {
        int m = 0;
        for (int s = tid + 1; s <= 60; s++) m += cnt[s];
        g_Mt[tid] = m;
    }
}

// ---------------------------------------------------------------------------
__global__ void build_B(const float* __restrict__ Wh, const float* __restrict__ Wx) {
    int idx = blockIdx.x * 256 + threadIdx.x;
    if (idx >= NG * KB) return;
    int k = idx / NG;
    int n = idx % NG;
    int nsrc = (n & 3) * 512 + (n >> 2);
    float v;
    if (k < KH)            v = Wh[(size_t)k * NG + nsrc];
    else if (k < KH + NE)  v = Wx[(size_t)(k - KH) * NG + nsrc];
    else                   v = 0.0f;
    g_B[(size_t)n * KB + k] = __float2half_rn(v);
}

// ---------------------------------------------------------------------------
__global__ void build_Ax(const int* __restrict__ in1, const int* __restrict__ in2,
                         const float* __restrict__ emb) {
    int w = blockIdx.x * 8 + (threadIdx.x >> 5);
    int lane = threadIdx.x & 31;
    if (w >= NT * NB2) return;
    int t   = w >> 10;
    int pos = w & 1023;
    if (pos >= g_Mt[t]) return;
    int b2 = g_perm[pos];
    int tok = (b2 < NB) ? in1[b2 * NT + t] : in2[(b2 - NB) * NT + t];
    const float* er = emb + (size_t)tok * NE;
    size_t base = (size_t)w * KX;
    for (int k = lane; k < KX; k += 32) {
        float v = (k < NE) ? er[k] : 0.0f;
        g_Ax[base + k] = __float2half_rn(v);
    }
}

// ---------------------------------------------------------------------------
// ALL recurrence steps in ONE launch. Grid (32, 16, 60), z = timestep.
// CTA tile 64x64. Fine-grained dependency: h chunk c of (t, rt64) needs
// producer col-CTAs 4c..4c+3 of (t-1, rt64). x chunks load first. 4 stages.
// ---------------------------------------------------------------------------
__global__ void __launch_bounds__(256, 3)
lstm_chain(const float* __restrict__ bias) {
    extern __shared__ char dsm[];
    float* zt = (float*)dsm;
    __shared__ float s_bias[64];

    const int tid  = threadIdx.x;
    const int wid  = tid >> 5;
    const int lane = tid & 31;
    const int t  = blockIdx.z;
    const int rt = blockIdx.y, ct = blockIdx.x;
    const int row0 = rt * 64, col0 = ct * 64;
    const bool active = (row0 < g_Mt[t]);
    const int wm0 = (wid & 3) * 16, wn0 = (wid >> 2) * 32;
    const uint32_t sm = smem_u32(dsm);
    const int gid = lane >> 2, tig = lane & 3;

    if (active) {
        if (tid < 64) {
            int u = ct * 16 + (tid >> 2), g = tid & 3;
            s_bias[tid] = bias[g * 512 + u] + ((g == 2) ? 1.0f : 0.0f);
        }

        float acc[4][4];
        #pragma unroll
        for (int j = 0; j < 4; j++)
            #pragma unroll
            for (int k = 0; k < 4; k++) acc[j][k] = 0.0f;

        {
            const int NCe = (t > 0) ? NCALL : 5;   // t=0: x-only
            const __half* aH = g_Abuf[t & 1] + (size_t)row0 * KH;
            const __half* aX = g_Ax + ((size_t)t * NB2 + row0) * KX;
            const __half* bRow = g_B + (size_t)col0 * KB;

            auto chunk_of = [&](int ci) { return (ci < 5) ? (8 + ci) : (ci - 5); };

            auto wait_group = [&](int ci) {
                if (t == 0 || ci < 5) return;
                int c = ci - 5;
                if (tid == 0) {
                    volatile int* f = &g_flag[t - 1][rt][c];
                    while (*f < 4) __nanosleep(32);
                }
                __syncthreads();
            };

            auto load_chunk = [&](int ci, int st) {
                int c = chunk_of(ci);
                uint32_t aB = sm + st * STAGE_BYTES;
                uint32_t bB = aB + 8192;
                const __half* bS = bRow + c * 64;
                #pragma unroll
                for (int i = 0; i < 2; i++) {
                    int idx = i * 256 + tid;
                    int n = idx >> 3, s = idx & 7;
                    cpasync16(bB + SWZ(n * 128 + s * 16), bS + (size_t)n * KB + s * 8);
                }
                const __half* aS;
                int stride;
                if (c < 8) { aS = aH + c * 64;       stride = KH; }
                else       { aS = aX + (c - 8) * 64; stride = KX; }
                #pragma unroll
                for (int i = 0; i < 2; i++) {
                    int idx = i * 256 + tid;
                    int r = idx >> 3, s = idx & 7;
                    cpasync16(aB + SWZ(r * 128 + s * 16), aS + (size_t)r * stride + s * 8);
                }
            };

            // prologue: first 4 chunks are x/dependency-free (t=0: 5 total)
            for (int s = 0; s < STAGES && s < NCe; s++) {
                wait_group(s);
                load_chunk(s, s);
                CP_COMMIT();
            }

            const int a_row = wm0 + (lane & 15);
            const int a_colb = 16 * (lane >> 4);
            const int b_row = wn0 + lane;
            for (int ci = 0; ci < NCe; ci++) {
                int st = ci & (STAGES - 1);
                int rem = NCe - 1 - ci;
                if (rem >= 3)      asm volatile("cp.async.wait_group 3;" ::: "memory");
                else if (rem == 2) asm volatile("cp.async.wait_group 2;" ::: "memory");
                else if (rem == 1) asm volatile("cp.async.wait_group 1;" ::: "memory");
                else               asm volatile("cp.async.wait_group 0;" ::: "memory");
                __syncthreads();

                uint32_t aB = sm + st * STAGE_BYTES;
                uint32_t bB = aB + 8192;
                #pragma unroll
                for (int kk = 0; kk < 4; kk++) {
                    uint32_t a[4];
                    uint32_t addr = aB + SWZ(a_row * 128 + kk * 32 + a_colb);
                    ldsm_x4(a[0], a[1], a[2], a[3], addr);
                    uint32_t blo[4], bhi[4];
                    uint32_t addr0 = bB + SWZ(b_row * 128 + kk * 32);
                    ldsm_x4(blo[0], blo[1], blo[2], blo[3], addr0);
                    uint32_t addr1 = bB + SWZ(b_row * 128 + kk * 32 + 16);
                    ldsm_x4(bhi[0], bhi[1], bhi[2], bhi[3], addr1);
                    #pragma unroll
                    for (int nf = 0; nf < 4; nf++)
                        mma_f16(acc[nf], a, blo[nf], bhi[nf]);
                }
                __syncthreads();
                if (ci + STAGES < NCe) {
                    wait_group(ci + STAGES);
                    load_chunk(ci + STAGES, st);
                    CP_COMMIT();
                }
            }
        }
        __syncthreads();   // all MMA smem reads done before z overwrite

        #pragma unroll
        for (int nf = 0; nf < 4; nf++) {
            int r = wm0 + gid;
            int cc = wn0 + nf * 8 + tig * 2;
            *reinterpret_cast<float2*>(&zt[r * ZS + cc]) =
                make_float2(acc[nf][0], acc[nf][1]);
            *reinterpret_cast<float2*>(&zt[(r + 8) * ZS + cc]) =
                make_float2(acc[nf][2], acc[nf][3]);
        }
        __syncthreads();

        // fused LSTM cell: 4 threads per row, 4 units each, coalesced float4 I/O
        {
            int row = tid >> 2;
            int ul0 = (tid & 3) * 4;
            size_t b = (size_t)row0 + row;
            bool valid = t < g_slp[b];
            float cold[4], hnew[4];
            float* hp = g_h + b * NH + ct * 16 + ul0;
            float* cp = g_c + b * NH + ct * 16 + ul0;
            if (t > 0) {
                *reinterpret_cast<float4*>(cold) = *reinterpret_cast<const float4*>(cp);
            } else {
                #pragma unroll
                for (int i = 0; i < 4; i++) cold[i] = 0.0f;
            }
            #pragma unroll
            for (int i = 0; i < 4; i++) {
                float4 z4 = *reinterpret_cast<const float4*>(&zt[row * ZS + (ul0 + i) * 4]);
                float4 b4 = *reinterpret_cast<const float4*>(&s_bias[(ul0 + i) * 4]);
                float zi = z4.x + b4.x;
                float zj = z4.y + b4.y;
                float zf = z4.z + b4.z;
                float zo = z4.w + b4.w;
                float nc = cold[i] * sigmf(zf) + sigmf(zi) * tanh_fast(zj);
                float nh = tanh_fast(nc) * sigmf(zo);
                cold[i] = nc; hnew[i] = nh;
            }
            if (valid) {
                *reinterpret_cast<float4*>(cp) = *reinterpret_cast<float4*>(cold);
                *reinterpret_cast<float4*>(hp) = *reinterpret_cast<float4*>(hnew);
                __half* an = g_Abuf[(t + 1) & 1] + b * KH + ct * 16 + ul0;
                __half2 h0, h1;
                h0.x = __float2half_rn(hnew[0]); h0.y = __float2half_rn(hnew[1]);
                h1.x = __float2half_rn(hnew[2]); h1.y = __float2half_rn(hnew[3]);
                *reinterpret_cast<__half2*>(an)     = h0;
                *reinterpret_cast<__half2*>(an + 2) = h1;
            }
        }
        __threadfence();   // make this CTA's writes visible before arrival
    }

    // arrive on this step's group flag (active or not)
    __syncthreads();
    if (tid == 0 && t < NT - 1) atomicAdd(&g_flag[t][rt][ct >> 2], 1);
}

// ---------------------------------------------------------------------------
__global__ void gemm128(const float* __restrict__ A, int lda,
                        const float* __restrict__ Bm, int ldb,
                        float* __restrict__ C, int ldc,
                        int K, const float* __restrict__ aux) {
    __shared__ float As[8][128];
    __shared__ float Bs[8][128];
    const int tid  = threadIdx.x;
    const int row0 = blockIdx.y * 128;
    const int col0 = blockIdx.x * 128;
    float acc[8][8];
    #pragma unroll
    for (int i = 0; i < 8; i++)
        #pragma unroll
        for (int j = 0; j < 8; j++) acc[i][j] = 0.0f;
    const int tr = (tid >> 4) << 3;
    const int tc = (tid & 15) << 3;
    for (int k0 = 0; k0 < K; k0 += 8) {
        #pragma unroll
        for (int i = 0; i < 4; i++) {
            int p = tid * 4 + i, ar = p >> 3, ak = p & 7;
            As[ak][ar] = (k0 + ak < K) ? A[(size_t)(row0 + ar) * lda + k0 + ak] : 0.0f;
        }
        #pragma unroll
        for (int i = 0; i < 4; i++) {
            int p = tid * 4 + i, bk = p >> 7, bc = p & 127;
            Bs[bk][bc] = (k0 + bk < K) ? Bm[(size_t)(k0 + bk) * ldb + col0 + bc] : 0.0f;
        }
        __syncthreads();
        #pragma unroll
        for (int kk = 0; kk < 8; kk++) {
            float ra[8], rb[8];
            #pragma unroll
            for (int i = 0; i < 8; i++) ra[i] = As[kk][tr + i];
            #pragma unroll
            for (int j = 0; j < 8; j++) rb[j] = Bs[kk][tc + j];
            #pragma unroll
            for (int i = 0; i < 8; i++)
                #pragma unroll
                for (int j = 0; j < 8; j++) acc[i][j] += ra[i] * rb[j];
        }
        __syncthreads();
    }
    #pragma unroll
    for (int i = 0; i < 8; i++)
        #pragma unroll
        for (int j = 0; j < 8; j++) {
            size_t idx = (size_t)(row0 + tr + i) * ldc + (col0 + tc + j);
            float v = acc[i][j] + aux[col0 + tc + j];
            C[idx] = v > 0.0f ? v : 0.0f;
        }
}

// ---------------------------------------------------------------------------
__global__ void combine(const int* __restrict__ sl1, const int* __restrict__ sl2) {
    int b = blockIdx.x;
    __shared__ float red[256];
    float len1 = (float)sl1[b] / (float)NT;
    float len2 = (float)sl2[b] / (float)NT;
    int p1 = g_pos[b], p2 = g_pos[NB + b];
    float lsum = 0.0f;
    float* hc = g_hc + (size_t)b * NHC;
    for (int k = threadIdx.x; k < NH + 1; k += 256) {
        float a = (k < NH) ? g_h[(size_t)p1 * NH + k] : len1;
        float d = (k < NH) ? g_h[(size_t)p2 * NH + k] : len2;
        float s = a - d;
        hc[k]        = a;
        hc[513 + k]  = d;
        hc[1026 + k] = s;
        hc[1540 + k] = a * d;
        lsum += s * s;
    }
    red[threadIdx.x] = lsum;
    __syncthreads();
    for (int s = 128; s > 0; s >>= 1) {
        if (threadIdx.x < s) red[threadIdx.x] += red[threadIdx.x + s];
        __syncthreads();
    }
    if (threadIdx.x == 0) hc[1539] = red[0];
}

__global__ void final_out(const float* __restrict__ W2, const float* __restrict__ b2,
                          float* __restrict__ out) {
    int b = blockIdx.x;
    __shared__ float s0[64], s1[64];
    float a0 = 0.0f, a1 = 0.0f;
    for (int k = threadIdx.x; k < NM; k += 64) {
        float e = g_e1[(size_t)b * NM + k];
        a0 += e * W2[k * 2 + 0];
        a1 += e * W2[k * 2 + 1];
    }
    s0[threadIdx.x] = a0;
    s1[threadIdx.x] = a1;
    __syncthreads();
    for (int s = 32; s > 0; s >>= 1) {
        if (threadIdx.x < s) { s0[threadIdx.x] += s0[threadIdx.x + s];
                               s1[threadIdx.x] += s1[threadIdx.x + s]; }
        __syncthreads();
    }
    if (threadIdx.x == 0) {
        out[b * 2 + 0] = s0[0] + b2[0];
        out[b * 2 + 1] = s1[0] + b2[1];
    }
}

// ---------------------------------------------------------------------------
extern "C" void kernel_launch(void* const* d_in, const int* in_sizes, int n_in,
                              void* d_out, int out_size) {
    const int*   in1 = (const int*)  d_in[0];
    const int*   in2 = (const int*)  d_in[1];
    const int*   sl1 = (const int*)  d_in[2];
    const int*   sl2 = (const int*)  d_in[3];
    const float* emb = (const float*)d_in[4];
    const float* lk  = (const float*)d_in[5];
    const float* lb  = (const float*)d_in[6];
    const float* W1  = (const float*)d_in[7];
    const float* b1  = (const float*)d_in[8];
    const float* W2  = (const float*)d_in[9];
    const float* b2  = (const float*)d_in[10];
    float* out = (float*)d_out;

    float *p_hc, *p_e1;
    cudaGetSymbolAddress((void**)&p_hc, g_hc);
    cudaGetSymbolAddress((void**)&p_e1, g_e1);

    cudaFuncSetAttribute(lstm_chain, cudaFuncAttributeMaxDynamicSharedMemorySize, GEMM_SMEM);

    const float* Wh = lk + (size_t)NE * NG;   // rows [300, 812)
    const float* Wx = lk;                     // rows [0, 300)

    sort_rows<<<1, NB2>>>(sl1, sl2);
    build_B<<<(NG * KB + 255) / 256, 256>>>(Wh, Wx);
    build_Ax<<<(NT * NB2 + 7) / 8, 256>>>(in1, in2, emb);

    // entire recurrence: one launch, group-flag-chained across steps
    lstm_chain<<<dim3(32, 16, NT), 256, GEMM_SMEM>>>(lb);

    combine<<<NB, 256>>>(sl1, sl2);
    gemm128<<<dim3(NM / 128, NB / 128), 256>>>(p_hc, NHC, W1, NM, p_e1, NM, NHC, b1);
    final_out<<<NB, 64>>>(W2, b2, out);
}